// round 6
// baseline (speedup 1.0000x reference)
#include <cuda_runtime.h>
#include <math.h>

// Problem constants (fixed by the dataset)
#define L_DIM 16384
#define H_DIM 1024

// Segment-parallel chunked scan:
//   block = TILE_H=32 channels x CHUNK=512 rows, TPB=288 (9 warps).
//   Warp s (s=1..8) scans segment s (64 rows) of the chunk from zero;
//   warp 0 scans the 64-row halo before the chunk (block-boundary warmup).
//   Segment partials are combined EXACTLY through SMEM (carry-in for seg s is
//   P_{s-1} = sum_j A^64^(s-1-j) * partial_j), then each warp emits
//   out[i] = local[i] + A^(i+1) * carry.
// vs rounds 1-5: serial chain per thread drops 192->64 rows, all 64 loads per
// thread are independent (huge MLP), halo amplification drops to 1.125x
// (136 MB total L2 traffic), and warp count rises to 9216 (~18 warps/SM).
// Only approximation: block-boundary truncation, error ~ A^65 * O(5) ~ 2e-6.
#define SEG    64
#define NSEG   8
#define CHUNK  (SEG * NSEG)        // 512
#define TILE_H 32
#define NWARP  (NSEG + 1)          // 9 (warp 0 = halo)
#define TPB    (32 * NWARP)        // 288

// 2 blocks/SM -> reg cap 113/thread; v[64] + overhead ~ 90 regs.
__global__ __launch_bounds__(TPB, 2)
void LI_scan_kernel(const float* __restrict__ x,
                    const float* __restrict__ tau,
                    float* __restrict__ out) {
    const int s  = threadIdx.x >> 5;              // segment id 0..8 (warp id)
    const int c  = threadIdx.x & 31;              // lane = channel within tile
    const int ch = blockIdx.y * TILE_H + c;
    const int chunk_start = blockIdx.x * CHUNK;
    const int row0 = chunk_start + (s - 1) * SEG; // s=0 -> halo rows (may be <0)

    const float A = expf(tau[ch]);

    __shared__ float sp[NWARP][TILE_H];

    const float* px = x + ch;
    float v[SEG];
    const bool valid = (row0 >= 0);               // block 0 has no halo rows
    float partial = 0.f;
    if (valid) {
        const int off = row0 * H_DIM;             // 32-bit offsets: L*H = 2^24
        #pragma unroll
        for (int j = 0; j < SEG; ++j)             // 64 independent LDG.32,
            v[j] = px[off + j * H_DIM];           // 128B coalesced per warp
        float a = 0.f;
        #pragma unroll
        for (int j = 0; j < SEG; ++j) {           // local inclusive scan
            a = fmaf(A, a, v[j]);
            v[j] = a;
        }
        partial = a;
    }
    sp[s][c] = partial;

    // A^SEG via 6 squarings (SEG = 64 = 2^6)
    float A64 = A;
    #pragma unroll
    for (int q = 0; q < 6; ++q) A64 *= A64;

    __syncthreads();

    if (s >= 1) {
        // Exact carry-in for this segment: P_{s-1} over the in-block partials.
        float carry = 0.f;
        for (int j = 0; j < s; ++j)
            carry = fmaf(A64, carry, sp[j][c]);
        // Emit: out[row0+j] = local[j] + A^(j+1) * carry
        float* po = out + ch;
        const int off = row0 * H_DIM;
        float pc = carry;
        #pragma unroll
        for (int j = 0; j < SEG; ++j) {
            pc *= A;
            __stcs(po + off + j * H_DIM, v[j] + pc);  // streaming store
        }
    }
}

extern "C" void kernel_launch(void* const* d_in, const int* in_sizes, int n_in,
                              void* d_out, int out_size) {
    const float* x   = (const float*)d_in[0];   // (L, H) fp32
    const float* tau = (const float*)d_in[1];   // (H,)   fp32
    float*       out = (float*)d_out;           // (L, H) fp32

    dim3 grid(L_DIM / CHUNK, H_DIM / TILE_H);   // (32, 32) = 1024 blocks
    LI_scan_kernel<<<grid, TPB>>>(x, tau, out);
}

// round 7
// speedup vs baseline: 1.4346x; 1.4346x over previous
#include <cuda_runtime.h>
#include <math.h>

// Problem constants (fixed by the dataset)
#define L_DIM 16384
#define H_DIM 1024

// R4 structure (best timed so far): block = CHUNK=64 rows x 256 channels,
// 128 threads, 2 channels/thread (float2), 8 blocks/SM, double-buffered loads.
// R7 change: halo K shrunk via measured error headroom. rel_err at K=64 was
// 1.1e-7 and truncation error scales as A^K, so threshold 2e-4 (K=40 for
// A=0.8) lands at ~2e-5 -- 43x under the 1e-3 tolerance -- while cutting
// read amplification 2.0x -> 1.625x and the per-warp serial chain 128 -> 104 rows.
#define CHUNK  64
#define GROUPS 4          // H / 256
#define TPB    128
#define BATCH  8          // outstanding LDG.64 per thread per buffer

__device__ __forceinline__ float2 ld2(const float* p) {
    return *reinterpret_cast<const float2*>(p);
}

__device__ __forceinline__ void loadB(float2 v[BATCH], const float* px, int off) {
#pragma unroll
    for (int j = 0; j < BATCH; ++j)
        v[j] = ld2(px + off + j * H_DIM);   // BATCH back-to-back LDG.64
}

__device__ __forceinline__ void procB(const float2 v[BATCH], float2 A, float2& acc,
                                      float* po, int off, bool store) {
#pragma unroll
    for (int j = 0; j < BATCH; ++j) {
        acc.x = fmaf(A.x, acc.x, v[j].x);
        acc.y = fmaf(A.y, acc.y, v[j].y);
        if (store)   // evict-first store: don't let out[] evict x[] halo lines from L2
            __stcs(reinterpret_cast<float2*>(po + off + j * H_DIM), acc);
    }
}

// 8 blocks/SM (1024 threads) -> 64-reg/thread budget. Buffers are 32 regs.
__global__ __launch_bounds__(TPB, 8)
void LI_scan_kernel(const float* __restrict__ x,
                    const float* __restrict__ tau,
                    float* __restrict__ out) {
    const int chunk_start = blockIdx.x * CHUNK;
    const int ch          = (blockIdx.y * TPB + threadIdx.x) * 2;

    // Per-channel decay A = exp(tau)
    float2 t = ld2(tau + ch);
    float2 A;
    A.x = expf(t.x); A.y = expf(t.y);

    // Runtime halo length K: smallest K with Amax^K < 2e-4.
    // Error scales as A^K; measured 1.1e-7 at K=64 (threshold 1e-6), so this
    // lands ~2e-5 against a 1e-3 tolerance. Rounded up to a BATCH multiple.
    // Falls back to exact full prefix if A ~ 1 (no usable decay).
    float amax = fmaxf(A.x, A.y);
    int K;
    if (!(amax < 0.999999f)) {
        K = chunk_start;                       // no usable decay: exact prefix
    } else if (amax <= 1e-12f) {
        K = 0;
    } else {
        float kf = logf(2e-4f) / logf(amax);   // both logs negative -> positive
        int   ki = (int)ceilf(kf);
        if (ki < 0) ki = 0;
        ki = (ki + BATCH - 1) & ~(BATCH - 1);  // round up to multiple of BATCH
        K = ki < chunk_start ? ki : chunk_start;  // chunk_start % BATCH == 0
    }

    // Block-uniform K (keeps batch loop structure aligned across the block)
    __shared__ int sK;
    if (threadIdx.x == 0) sK = 0;
    __syncthreads();
    atomicMax(&sK, K);
    __syncthreads();
    K = sK;

    const float* px = x + ch;
    float*       po = out + ch;

    float2 acc = make_float2(0.f, 0.f);

    // ---- Fused halo + main loop, software-pipelined (double buffer) ----
    // Rows [chunk_start-K, chunk_start) warm up acc (no stores);
    // rows [chunk_start, chunk_start+CHUNK) also store. K and CHUNK are both
    // multiples of BATCH, so each batch is uniformly halo or main.
    // 32-bit element offsets: L*H = 2^24 fits comfortably.
    int off        = (chunk_start - K) * H_DIM;  // current batch offset
    const int off0 = chunk_start * H_DIM;        // first storing offset
    const int nb   = (K + CHUNK) / BATCH;        // >= CHUNK/BATCH = 8

    float2 v0[BATCH], v1[BATCH];
    loadB(v0, px, off);
    int b = 0;
    while (true) {
        if (b + 1 < nb) loadB(v1, px, off + BATCH * H_DIM);  // prefetch next batch
        procB(v0, A, acc, po, off, off >= off0);
        off += BATCH * H_DIM; if (++b >= nb) break;
        if (b + 1 < nb) loadB(v0, px, off + BATCH * H_DIM);  // prefetch next batch
        procB(v1, A, acc, po, off, off >= off0);
        off += BATCH * H_DIM; if (++b >= nb) break;
    }
}

extern "C" void kernel_launch(void* const* d_in, const int* in_sizes, int n_in,
                              void* d_out, int out_size) {
    const float* x   = (const float*)d_in[0];   // (L, H) fp32
    const float* tau = (const float*)d_in[1];   // (H,)   fp32
    float*       out = (float*)d_out;           // (L, H) fp32

    dim3 grid(L_DIM / CHUNK, GROUPS);
    LI_scan_kernel<<<grid, TPB>>>(x, tau, out);
}